// round 17
// baseline (speedup 1.0000x reference)
#include <cuda_runtime.h>

// SmoothLDDTLoss, b=2, n=4096. Upper-triangle only. Single fused kernel.
// Register blocking x4: 128 threads/block, each thread owns FOUR i-points
// (i0 + {0,128,256,384} + t) so every j-tile LDS + loop iteration feeds
// four pairs. Coords pre-scaled by 64. 1024-entry nearest-sample eps LUT
// (midpoint; stores 128+eps so one accumulator per i-point carries
// 128*count + sum). J-tiles partitioned (non-nucleic first, deterministic
// ballot ranks) -> constant cutoffs in the inner loops. Diag tiles keep
// original j order for the j>i test.

#define NPTS   4096
#define NB     2
#define ITILE  512
#define JTILE  64
#define NTILES 288                 // sum_{ti=0..7} (64 - 8*ti)
#define TOTAL_BLKS (NTILES * NB)
#define THREADS 128
#define IPT    4                   // i-points per thread

#define NSEG   1024                // d64 in [0,1024): 16 A range
#define CSCALE 64.0f

typedef unsigned long long ull;

__device__ float g_psum[NB][NTILES];
__device__ float g_pcnt[NB][NTILES];
__device__ unsigned int g_ticket = 0;

__device__ __forceinline__ ull pk2(float lo, float hi) {
    ull r; asm("mov.b64 %0,{%1,%2};" : "=l"(r) : "f"(lo), "f"(hi)); return r;
}
__device__ __forceinline__ void upk2(float& lo, float& hi, ull v) {
    asm("mov.b64 {%0,%1},%2;" : "=f"(lo), "=f"(hi) : "l"(v));
}
__device__ __forceinline__ ull fma2(ull a, ull b, ull c) {
    ull d; asm("fma.rn.f32x2 %0,%1,%2,%3;" : "=l"(d) : "l"(a), "l"(b), "l"(c)); return d;
}
__device__ __forceinline__ ull add2(ull a, ull b) {
    ull d; asm("add.rn.f32x2 %0,%1,%2;" : "=l"(d) : "l"(a), "l"(b)); return d;
}
__device__ __forceinline__ float sqrt_a(float x) {
    float r; asm("sqrt.approx.f32 %0,%1;" : "=f"(r) : "f"(x)); return r;
}

__device__ __forceinline__ float sigf(float z) {
    return 1.0f / (1.0f + __expf(-z));
}
__device__ __forceinline__ float eps_exact(float d) {
    return 0.25f * (sigf(0.5f - d) + sigf(1.0f - d) +
                    sigf(2.0f - d) + sigf(4.0f - d));
}

// One pair: packed (pred|true) distance chain -> td and 128+eps(d).
__device__ __forceinline__ void pair_eval(
    const ulonglong2 A, const ull Z, const ull EPS2,
    ull ix, ull iy, ull iz, const float* __restrict__ lut,
    float& td, float& epsP)
{
    const ull dx = add2(ix, A.x);
    const ull dy = add2(iy, A.y);
    const ull dz = add2(iz, Z);
    ull q = fma2(dx, dx, EPS2);
    q = fma2(dy, dy, q);
    q = fma2(dz, dz, q);
    float pd2, td2; upk2(pd2, td2, q);
    const float pd = sqrt_a(pd2);
    td = sqrt_a(td2);
    const float dc = fminf(fabsf(td - pd), 1023.0f);
    epsP = lut[__float2int_rz(dc)];
}

__global__ __launch_bounds__(THREADS, 4) void lddt_fused_kernel(
    const float* __restrict__ pred,
    const float* __restrict__ truec,
    const unsigned char* __restrict__ dna,
    const unsigned char* __restrict__ rna,
    float* __restrict__ out)
{
    __shared__ float      lut[NSEG];       // 4 KB
    __shared__ ulonglong2 shXY[JTILE];     // 1 KB
    __shared__ ull        shZ[JTILE];      // 512 B
    __shared__ float      shNJ[JTILE];     // diag tiles only
    __shared__ float red[THREADS], redc[THREADS];
    __shared__ float lddt_sh[NB];
    __shared__ unsigned int amLast;
    __shared__ int sWarpNuc[2];
    __shared__ int sNNon;

    const int b    = blockIdx.y;
    const int tlin = blockIdx.x;
    const int t    = threadIdx.x;

    // Nearest-sample eps LUT: entry k = eps at midpoint (k+0.5)/64, +128.
    for (int k = t; k < NSEG; k += THREADS) {
        lut[k] = 128.0f + eps_exact(((float)k + 0.5f) * (1.0f / CSCALE));
    }

    // Decode linear tile id -> (ti, tj); cum(ti) = 4*ti*(17-ti).
    int ti = (int)((17.0f - sqrtf((float)(289 - tlin))) * 0.5f);
    if (ti > 7) ti = 7;
    if (ti < 0) ti = 0;
    while (ti > 0 && 4 * ti * (17 - ti) > tlin) --ti;
    while (4 * (ti + 1) * (16 - ti) <= tlin) ++ti;
    const int tj = 8 * ti + (tlin - 4 * ti * (17 - ti));
    const bool diag = (tj < 8 * ti + 8);

    const int i0 = ti * ITILE;
    const int j0 = tj * JTILE;

    // ---- Stage the j tile (partitioned for non-diag tiles) ----
    float jpx = 0, jpy = 0, jpz = 0, jtx = 0, jty = 0, jtz = 0;
    bool nuc = false;
    if (t < JTILE) {
        const int j = j0 + t;
        const float* pp = pred  + ((size_t)b * NPTS + j) * 3;
        const float* tp = truec + ((size_t)b * NPTS + j) * 3;
        jpx = pp[0]; jpy = pp[1]; jpz = pp[2];
        jtx = tp[0]; jty = tp[1]; jtz = tp[2];
        nuc = (dna[b * NPTS + j] | rna[b * NPTS + j]) != 0;
    }
    const unsigned bal = __ballot_sync(0xffffffffu, nuc);
    if (t < JTILE && (t & 31) == 0) sWarpNuc[t >> 5] = __popc(bal);
    __syncthreads();

    int pos = t;
    if (!diag && t < JTILE) {
        const int nNon = JTILE - sWarpNuc[0] - sWarpNuc[1];
        const int lt = __popc(bal & ((1u << (t & 31)) - 1u));
        pos = nuc ? (nNon + lt + ((t >= 32) ? sWarpNuc[0] : 0))
                  : ((t & 31) - lt + ((t >= 32) ? (32 - sWarpNuc[0]) : 0));
        if (t == 0) sNNon = nNon;
    }
    if (diag && t == 0) sNNon = 0;
    if (t < JTILE) {
        ulonglong2 xy;
        xy.x = pk2(-jpx * CSCALE, -jtx * CSCALE);
        xy.y = pk2(-jpy * CSCALE, -jty * CSCALE);
        shXY[pos] = xy;
        shZ[pos]  = pk2(-jpz * CSCALE, -jtz * CSCALE);
        shNJ[pos] = nuc ? 1.0f : 0.0f;
    }

    // ---- This thread's FOUR i points, packed (pred|true) per component ----
    ull ix[IPT], iy[IPT], iz[IPT];
    float ni960[IPT], csn[IPT];
    int thresh[IPT];
    #pragma unroll
    for (int k = 0; k < IPT; ++k) {
        const int ik = i0 + k * THREADS + t;
        const float* pp = pred  + ((size_t)b * NPTS + ik) * 3;
        const float* tp = truec + ((size_t)b * NPTS + ik) * 3;
        ix[k] = pk2(pp[0] * CSCALE, tp[0] * CSCALE);
        iy[k] = pk2(pp[1] * CSCALE, tp[1] * CSCALE);
        iz[k] = pk2(pp[2] * CSCALE, tp[2] * CSCALE);
        const bool inuc = (dna[b * NPTS + ik] | rna[b * NPTS + ik]) != 0;
        ni960[k] = inuc ? 960.0f : 0.0f;
        csn[k]   = inuc ? 1920.0f : 960.0f;
        thresh[k] = ik - j0;
    }

    __syncthreads();
    const int nNon = sNNon;
    const ull EPS2 = pk2(4.096e-9f, 4.096e-9f);    // 1e-12 * 64^2

    float acc[IPT] = {0.0f, 0.0f, 0.0f, 0.0f};     // 128*cnt + sum each
    if (!diag) {
        int jj = 0;
        #pragma unroll 2
        for (; jj < nNon; ++jj) {                  // non-nucleic j: 15A
            const ulonglong2 A = shXY[jj];
            const ull        Z = shZ[jj];
            #pragma unroll
            for (int k = 0; k < IPT; ++k) {
                float td, e;
                pair_eval(A, Z, EPS2, ix[k], iy[k], iz[k], lut, td, e);
                if (td < 960.0f) acc[k] += e;
            }
        }
        #pragma unroll 2
        for (; jj < JTILE; ++jj) {                 // nucleic j: 15/30A
            const ulonglong2 A = shXY[jj];
            const ull        Z = shZ[jj];
            #pragma unroll
            for (int k = 0; k < IPT; ++k) {
                float td, e;
                pair_eval(A, Z, EPS2, ix[k], iy[k], iz[k], lut, td, e);
                if (td < csn[k]) acc[k] += e;
            }
        }
    } else {
        #pragma unroll 2
        for (int jj = 0; jj < JTILE; ++jj) {
            const ulonglong2 A = shXY[jj];
            const ull        Z = shZ[jj];
            const float      nj = shNJ[jj];
            #pragma unroll
            for (int k = 0; k < IPT; ++k) {
                float td, e;
                pair_eval(A, Z, EPS2, ix[k], iy[k], iz[k], lut, td, e);
                const float cs = fmaf(nj, ni960[k], 960.0f);
                if ((td < cs) && (jj > thresh[k])) acc[k] += e;
            }
        }
    }

    // Split acc = 128*cnt + sum per i-point (cnt <= 64, sum < 64 each).
    float cntT = 0.0f, sumT = 0.0f;
    #pragma unroll
    for (int k = 0; k < IPT; ++k) {
        const float c = truncf(acc[k] * 0.0078125f);
        cntT += c;
        sumT += fmaf(c, -128.0f, acc[k]);
    }

    // Block reduction (counts exact: integers < 2^24).
    red[t] = sumT; redc[t] = cntT;
    __syncthreads();
    #pragma unroll
    for (int s = THREADS / 2; s > 0; s >>= 1) {
        if (t < s) { red[t] += red[t + s]; redc[t] += redc[t + s]; }
        __syncthreads();
    }

    if (t == 0) {
        g_psum[b][tlin] = red[0];
        g_pcnt[b][tlin] = redc[0];
        __threadfence();
        const unsigned int old = atomicAdd(&g_ticket, 1u);
        amLast = (old == TOTAL_BLKS - 1) ? 1u : 0u;
    }
    __syncthreads();

    if (amLast) {
        // Deterministic finalize: half-block per batch, fixed order.
        const int bb = t >> 6;        // 0 or 1
        const int l  = t & 63;
        float s = 0.0f, c = 0.0f;
        for (int p = l; p < NTILES; p += 64) {
            s += g_psum[bb][p];
            c += g_pcnt[bb][p];
        }
        red[t] = s; redc[t] = c;
        __syncthreads();
        #pragma unroll
        for (int k = 32; k > 0; k >>= 1) {
            if (l < k) { red[t] += red[t + k]; redc[t] += redc[t + k]; }
            __syncthreads();
        }
        if (l == 0) lddt_sh[bb] = red[t] / fmaxf(redc[t], 1.0f);
        __syncthreads();
        if (t == 0) {
            out[0] = 1.0f - 0.5f * (lddt_sh[0] + lddt_sh[1]);
            g_ticket = 0;   // reset for next graph replay
        }
    }
}

extern "C" void kernel_launch(void* const* d_in, const int* in_sizes, int n_in,
                              void* d_out, int out_size)
{
    const float*         pred  = (const float*)d_in[0];
    const float*         truec = (const float*)d_in[1];
    const unsigned char* dna   = (const unsigned char*)d_in[2];
    const unsigned char* rna   = (const unsigned char*)d_in[3];

    dim3 grid(NTILES, NB);
    lddt_fused_kernel<<<grid, THREADS>>>(pred, truec, dna, rna, (float*)d_out);
}